// round 6
// baseline (speedup 1.0000x reference)
#include <cuda_runtime.h>

// out[b,v,h,w] = sum_c R[h,v,c] * feats[b,c,h,w]
// R is block-sparse RoPE: each 2x2 channel-pair block (v=2p, 2p+1) is
//   [ c00 c01 ]   applied to [ x_even ]
//   [ c10 c11 ]              [ x_odd  ]
// with coefficients read straight from the dense R input to match the
// reference bit-for-bit (no cos/sin recomputation).
//
// B=16, C=256, H=128, W=128. feats/out layout: [b,c,h,w], w contiguous.
// One warp handles one (b, pair, h) row of W=128 floats: lane i owns
// float4 at w = 4*i. Even/odd channel are H*W = 16384 floats apart.

#define B_DIM 16
#define C_DIM 256
#define H_DIM 128
#define W_DIM 128
#define HW (H_DIM * W_DIM)          // 16384
#define NPAIR (C_DIM / 2)            // 128
#define THREADS 256

__global__ void __launch_bounds__(THREADS, 8)
rope_pair_kernel(const float* __restrict__ feats,
                 const float* __restrict__ R,
                 float* __restrict__ out)
{
    // Linear thread id over (b, pair, h, w4): 16 * 128 * 128 * 32 = 8,388,608
    unsigned int t = blockIdx.x * THREADS + threadIdx.x;

    unsigned int w4 = t & 31u;            // lane: which float4 in the row
    unsigned int h  = (t >> 5) & 127u;    // row position
    unsigned int cp = (t >> 12) & 127u;   // channel pair
    unsigned int b  = t >> 19;            // batch

    unsigned int v = cp << 1;             // even channel index

    // 2x2 rotation block, warp-uniform loads (single transaction, L2-hit)
    const float* __restrict__ Rblk = R + (size_t)h * (C_DIM * C_DIM) + (size_t)v * C_DIM + v;
    float c00 = __ldg(Rblk + 0);          // row v,   col v
    float c01 = __ldg(Rblk + 1);          // row v,   col v+1
    float c10 = __ldg(Rblk + C_DIM);      // row v+1, col v
    float c11 = __ldg(Rblk + C_DIM + 1);  // row v+1, col v+1

    unsigned int base = ((b * C_DIM + v) * H_DIM + h) * W_DIM + (w4 << 2);

    float4 xe = *reinterpret_cast<const float4*>(feats + base);        // channel v
    float4 xo = *reinterpret_cast<const float4*>(feats + base + HW);   // channel v+1

    float4 ye, yo;
    ye.x = fmaf(c00, xe.x, c01 * xo.x);
    ye.y = fmaf(c00, xe.y, c01 * xo.y);
    ye.z = fmaf(c00, xe.z, c01 * xo.z);
    ye.w = fmaf(c00, xe.w, c01 * xo.w);

    yo.x = fmaf(c10, xe.x, c11 * xo.x);
    yo.y = fmaf(c10, xe.y, c11 * xo.y);
    yo.z = fmaf(c10, xe.z, c11 * xo.z);
    yo.w = fmaf(c10, xe.w, c11 * xo.w);

    *reinterpret_cast<float4*>(out + base)      = ye;
    *reinterpret_cast<float4*>(out + base + HW) = yo;
}

extern "C" void kernel_launch(void* const* d_in, const int* in_sizes, int n_in,
                              void* d_out, int out_size)
{
    const float* feats = (const float*)d_in[0];
    const float* R     = (const float*)d_in[1];
    // Defensive: feats (67,108,864 elems) is larger than R (8,388,608 elems)
    if (n_in >= 2 && in_sizes[0] < in_sizes[1]) {
        const float* tmp = feats; feats = R; R = tmp;
    }
    float* out = (float*)d_out;

    // 8,388,608 threads / 256 = 32,768 blocks
    const unsigned int total_threads = (unsigned int)B_DIM * NPAIR * H_DIM * (W_DIM / 4);
    rope_pair_kernel<<<total_threads / THREADS, THREADS>>>(feats, R, out);
}